// round 1
// baseline (speedup 1.0000x reference)
#include <cuda_runtime.h>
#include <cstdint>

#define NPTS   16384
#define NB     4
#define MPER   4096
#define NCENT  (NB*MPER)          // 16384 centroids
#define KNBR   33                 // K+1
#define NEDGE  (NCENT*KNBR)       // 540672 edges
#define H1DIM  128
#define H2DIM  256
#define CDIM   32
#define R2CONST 0.04f

#define OUT_POS_OFF   (NCENT*H2DIM)          // 4194304
#define OUT_BATCH_OFF (OUT_POS_OFF + NCENT*3)

// -------------------- device scratch (no allocations allowed) --------------
__device__ int   g_fps[NCENT];                      // local FPS idx per centroid
__device__ int   g_gidx[NCENT];                     // global idx per centroid
__device__ float g_cent[NCENT*3];                   // centroid coords
__device__ int   g_nbr[NEDGE];                      // neighbor global idx (padded w/ self)
__device__ float g_A  [(size_t)NB*NPTS*H1DIM];      // x @ W1[:32] + b1   (32 MB)
__device__ float g_H1 [(size_t)NEDGE*H1DIM];        // relu layer-1       (277 MB)
__device__ float g_H2 [(size_t)NEDGE*H2DIM];        // relu layer-2       (553 MB)
__device__ float g_agg[(size_t)NCENT*H2DIM];        // segment max        (16 MB)

// -------------------- 1) farthest point sampling ---------------------------
// One CTA per cloud. Coords in smem (192KB), per-thread mind in registers.
__global__ void __launch_bounds__(1024,1) fps_kernel(const float* __restrict__ pos) {
    int b = blockIdx.x;
    extern __shared__ float sm[];
    float* Xs = sm; float* Ys = sm + NPTS; float* Zs = sm + 2*NPTS;
    __shared__ unsigned long long wkey[32];
    __shared__ float qsh[3];
    const float* p = pos + (size_t)b*NPTS*3;
    int tid = threadIdx.x;
    for (int i = tid; i < NPTS; i += 1024) {
        Xs[i] = p[3*i]; Ys[i] = p[3*i+1]; Zs[i] = p[3*i+2];
    }
    __syncthreads();
    float qx = Xs[0], qy = Ys[0], qz = Zs[0];
    int base = tid * 16;
    float M[16];
#pragma unroll
    for (int k = 0; k < 16; k++) {
        float dx = Xs[base+k]-qx, dy = Ys[base+k]-qy, dz = Zs[base+k]-qz;
        M[k] = fmaf(dz,dz,fmaf(dy,dy,dx*dx));
    }
    if (tid == 0) g_fps[b*MPER] = 0;
    int lane = tid & 31, wid = tid >> 5;
    for (int t = 1; t < MPER; t++) {
        // argmax over current mind (first-index tie-break via complemented idx)
        float best = -1.0f; int bi = base;
#pragma unroll
        for (int k = 0; k < 16; k++) if (M[k] > best) { best = M[k]; bi = base + k; }
        unsigned long long key =
            ((unsigned long long)__float_as_uint(best) << 32) | (unsigned)(NPTS-1-bi);
#pragma unroll
        for (int off = 16; off > 0; off >>= 1) {
            unsigned long long o = __shfl_down_sync(0xffffffffu, key, off);
            if (o > key) key = o;
        }
        if (lane == 0) wkey[wid] = key;
        __syncthreads();
        if (wid == 0) {
            key = wkey[lane];
#pragma unroll
            for (int off = 16; off > 0; off >>= 1) {
                unsigned long long o = __shfl_down_sync(0xffffffffu, key, off);
                if (o > key) key = o;
            }
            if (lane == 0) {
                int sel = NPTS - 1 - (int)(key & 0xffffffffu);
                g_fps[b*MPER + t] = sel;
                qsh[0] = Xs[sel]; qsh[1] = Ys[sel]; qsh[2] = Zs[sel];
            }
        }
        __syncthreads();
        qx = qsh[0]; qy = qsh[1]; qz = qsh[2];
#pragma unroll
        for (int k = 0; k < 16; k++) {
            float dx = Xs[base+k]-qx, dy = Ys[base+k]-qy, dz = Zs[base+k]-qz;
            float d2 = fmaf(dz,dz,fmaf(dy,dy,dx*dx));
            M[k] = fminf(M[k], d2);
        }
    }
}

// -------------------- 2) gather centroids + write pos/batch outputs --------
__global__ void gather_kernel(const float* __restrict__ pos,
                              const int* __restrict__ batch,
                              float* __restrict__ dout) {
    int i = blockIdx.x*blockDim.x + threadIdx.x;
    if (i >= NCENT) return;
    int b = i >> 12;                 // / MPER
    int sel = g_fps[i];
    int g = b*NPTS + sel;
    float x = pos[3*g], y = pos[3*g+1], z = pos[3*g+2];
    g_cent[3*i] = x; g_cent[3*i+1] = y; g_cent[3*i+2] = z;
    g_gidx[i] = g;
    dout[OUT_POS_OFF + 3*i]   = x;
    dout[OUT_POS_OFF + 3*i+1] = y;
    dout[OUT_POS_OFF + 3*i+2] = z;
    dout[OUT_BATCH_OFF + i]   = (float)batch[g];
}

// -------------------- 3) ball query: 33 nearest within r -------------------
#define BQ_TILE 2048
#define BQ_CAP  1024
__global__ void __launch_bounds__(256,1) ballquery_kernel(const float* __restrict__ pos) {
    extern __shared__ float sm[];
    float* Xs = sm; float* Ys = sm + BQ_TILE; float* Zs = sm + 2*BQ_TILE;
    unsigned long long* buf = (unsigned long long*)(sm + 3*BQ_TILE);
    int tid = threadIdx.x;
    int wid = tid >> 5, lane = tid & 31;
    int c = blockIdx.x*8 + wid;            // 8 centroids per block, same cloud
    int cloud = c >> 12;
    const float* pcloud = pos + (size_t)cloud*NPTS*3;
    float cx = g_cent[3*c], cy = g_cent[3*c+1], cz = g_cent[3*c+2];
    unsigned long long* mybuf = buf + (size_t)wid*BQ_CAP;
    int cnt = 0;
    for (int tile = 0; tile < NPTS/BQ_TILE; ++tile) {
        for (int i = tid; i < BQ_TILE; i += 256) {
            int pidx = tile*BQ_TILE + i;
            Xs[i] = pcloud[3*pidx]; Ys[i] = pcloud[3*pidx+1]; Zs[i] = pcloud[3*pidx+2];
        }
        __syncthreads();
        for (int i = lane; i < BQ_TILE; i += 32) {
            float dx = Xs[i]-cx, dy = Ys[i]-cy, dz = Zs[i]-cz;
            float d2 = fmaf(dz,dz,fmaf(dy,dy,dx*dx));
            bool hit = (d2 <= R2CONST);
            unsigned m = __ballot_sync(0xffffffffu, hit);
            int pre = __popc(m & ((1u << lane) - 1u));
            if (hit) {
                int slot = cnt + pre;
                if (slot < BQ_CAP)
                    mybuf[slot] = ((unsigned long long)__float_as_uint(d2) << 32)
                                | (unsigned)(tile*BQ_TILE + i);
            }
            cnt += __popc(m);
        }
        __syncthreads();
    }
    if (cnt > BQ_CAP) cnt = BQ_CAP;
    int selfg = g_gidx[c];
    // extract 33 smallest keys (d2 bits, idx) -> lower idx wins ties
    for (int it = 0; it < KNBR; ++it) {
        unsigned long long mn = ~0ull;
        for (int j = lane; j < cnt; j += 32) {
            unsigned long long v = mybuf[j];
            if (v < mn) mn = v;
        }
#pragma unroll
        for (int off = 16; off > 0; off >>= 1) {
            unsigned long long o = __shfl_down_sync(0xffffffffu, mn, off);
            if (o < mn) mn = o;
        }
        mn = __shfl_sync(0xffffffffu, mn, 0);
        int nbr;
        if (mn == ~0ull) {
            nbr = selfg;   // fewer than 33 in radius: pad with self (max-invariant)
        } else {
            nbr = cloud*NPTS + (int)(mn & 0xffffffffu);
            for (int j = lane; j < cnt; j += 32)
                if (mybuf[j] == mn) mybuf[j] = ~0ull;
        }
        if (lane == 0) g_nbr[c*KNBR + it] = nbr;
    }
}

// -------------------- 4) per-point layer-1 x-part: A = x@W1[:32] + b1 ------
__global__ void pfeat_kernel(const float* __restrict__ x,
                             const float* __restrict__ lw1,
                             const float* __restrict__ lb1) {
    int idx = blockIdx.x*blockDim.x + threadIdx.x;   // NB*NPTS*128
    int p = idx >> 7, ch = idx & 127;
    float acc = lb1[ch];
    const float* xp = x + (size_t)p*CDIM;
#pragma unroll
    for (int j = 0; j < CDIM; j++)
        acc = fmaf(xp[j], lw1[j*H1DIM + ch], acc);
    g_A[(size_t)p*H1DIM + ch] = acc;
}

// -------------------- 5) per-edge layer-1: H1 = relu(A[col] + dpos@W1[32:]) -
__global__ void eh1_kernel(const float* __restrict__ pos,
                           const float* __restrict__ lw1) {
    int idx = blockIdx.x*blockDim.x + threadIdx.x;   // NEDGE*128 = 69,206,016
    int e = idx >> 7, k = idx & 127;
    int c = e / KNBR;
    int col = g_nbr[e];
    float dx = pos[3*col]   - g_cent[3*c];
    float dy = pos[3*col+1] - g_cent[3*c+1];
    float dz = pos[3*col+2] - g_cent[3*c+2];
    float h = g_A[(size_t)col*H1DIM + k];
    h = fmaf(dx, lw1[32*H1DIM + k], h);
    h = fmaf(dy, lw1[33*H1DIM + k], h);
    h = fmaf(dz, lw1[34*H1DIM + k], h);
    g_H1[(size_t)e*H1DIM + k] = fmaxf(h, 0.0f);
}

// -------------------- 6) tiled SGEMM, C = relu(A@B + bias), N=256 ----------
__global__ void __launch_bounds__(256) sgemm_kernel(const float* __restrict__ A,
                                                    const float* __restrict__ Bw,
                                                    const float* __restrict__ bias,
                                                    float* __restrict__ C,
                                                    int Kdim) {
    __shared__ float As[8][128];
    __shared__ float Bs[8][128];
    int t = threadIdx.x;
    int tx = t & 15, ty = t >> 4;
    int m0 = blockIdx.x * 128, n0 = blockIdx.y * 128;
    float acc[8][8];
#pragma unroll
    for (int i = 0; i < 8; i++)
#pragma unroll
        for (int j = 0; j < 8; j++) acc[i][j] = 0.f;
    int r  = t >> 1, cc4 = (t & 1) * 4;
    int r2 = t >> 5, c2  = (t & 31) * 4;
    for (int k0 = 0; k0 < Kdim; k0 += 8) {
        float4 av = *(const float4*)(A + (size_t)(m0 + r)*Kdim + k0 + cc4);
        As[cc4+0][r] = av.x; As[cc4+1][r] = av.y; As[cc4+2][r] = av.z; As[cc4+3][r] = av.w;
        *(float4*)(&Bs[r2][c2]) = *(const float4*)(Bw + (size_t)(k0 + r2)*256 + n0 + c2);
        __syncthreads();
#pragma unroll
        for (int k = 0; k < 8; k++) {
            float a[8], bb[8];
#pragma unroll
            for (int i = 0; i < 8; i++) a[i]  = As[k][ty*8 + i];
#pragma unroll
            for (int j = 0; j < 8; j++) bb[j] = Bs[k][tx*8 + j];
#pragma unroll
            for (int i = 0; i < 8; i++)
#pragma unroll
                for (int j = 0; j < 8; j++) acc[i][j] = fmaf(a[i], bb[j], acc[i][j]);
        }
        __syncthreads();
    }
#pragma unroll
    for (int i = 0; i < 8; i++) {
        size_t row = (size_t)m0 + ty*8 + i;
#pragma unroll
        for (int j = 0; j < 8; j++) {
            int colI = n0 + tx*8 + j;
            float v = acc[i][j] + bias[colI];
            C[row*256 + colI] = fmaxf(v, 0.f);
        }
    }
}

// -------------------- 7) segment max over fixed 33-edge groups -------------
__global__ void segmax_kernel() {
    int idx = blockIdx.x*blockDim.x + threadIdx.x;   // NCENT*256
    int g = idx >> 8, ch = idx & 255;
    float m = 0.f;  // all h2 >= 0 (relu), group nonempty
    const float* h2 = g_H2 + (size_t)g*KNBR*H2DIM + ch;
#pragma unroll
    for (int s = 0; s < KNBR; s++) m = fmaxf(m, h2[(size_t)s*H2DIM]);
    g_agg[(size_t)g*H2DIM + ch] = m;
}

// -------------------- launch ------------------------------------------------
extern "C" void kernel_launch(void* const* d_in, const int* in_sizes, int n_in,
                              void* d_out, int out_size) {
    const float* x     = (const float*)d_in[0];
    const float* pos   = (const float*)d_in[1];
    const int*   batch = (const int*)  d_in[2];
    const float* lw1   = (const float*)d_in[3];
    const float* lb1   = (const float*)d_in[4];
    const float* lw2   = (const float*)d_in[5];
    const float* lb2   = (const float*)d_in[6];
    const float* gw1   = (const float*)d_in[7];
    const float* gb1   = (const float*)d_in[8];
    float* dout = (float*)d_out;

    // idempotent attribute sets (host-side, capture-safe)
    cudaFuncSetAttribute(fps_kernel, cudaFuncAttributeMaxDynamicSharedMemorySize,
                         3*NPTS*(int)sizeof(float));
    int bq_smem = 3*BQ_TILE*(int)sizeof(float) + 8*BQ_CAP*(int)sizeof(unsigned long long);
    cudaFuncSetAttribute(ballquery_kernel, cudaFuncAttributeMaxDynamicSharedMemorySize,
                         bq_smem);

    void *pH1 = nullptr, *pH2 = nullptr, *pAgg = nullptr;
    cudaGetSymbolAddress(&pH1,  g_H1);
    cudaGetSymbolAddress(&pH2,  g_H2);
    cudaGetSymbolAddress(&pAgg, g_agg);

    fps_kernel<<<NB, 1024, 3*NPTS*sizeof(float)>>>(pos);
    gather_kernel<<<NCENT/256, 256>>>(pos, batch, dout);
    ballquery_kernel<<<NCENT/8, 256, bq_smem>>>(pos);
    pfeat_kernel<<<(NB*NPTS*H1DIM)/256, 256>>>(x, lw1, lb1);
    eh1_kernel<<<(NEDGE*H1DIM)/256, 256>>>(pos, lw1);
    sgemm_kernel<<<dim3(NEDGE/128, 2), 256>>>((const float*)pH1, lw2, lb2,
                                              (float*)pH2, H1DIM);
    segmax_kernel<<<(NCENT*H2DIM)/256, 256>>>();
    sgemm_kernel<<<dim3(NCENT/128, 2), 256>>>((const float*)pAgg, gw1, gb1,
                                              dout, H2DIM);
}